// round 13
// baseline (speedup 1.0000x reference)
#include <cuda_runtime.h>
#include <cuda_bf16.h>
#include <cstdint>

// ---------------------------------------------------------------------------
// y = x @ Mf + cf  (exact collapse of the 9-layer linear chain), main pass on
// tensor cores via mma.sync.m16n8k8 tf32 (sm_80+ PTX -> HMMA on sm_103).
// R13: 4-deep cp.async pipeline (prefetch distance 3, 32-k chunks) so the
// staging latency is covered by ~3 warp-rounds of compute; B transposed in
// smem (pitch 788) for conflict-free fragment loads.
// ---------------------------------------------------------------------------

#define BSZ     65536
#define KDIM    784
#define NOUT    10
#define CTPB    256
#define MTPB    256               // 8 warps
#define WROWS   16                // rows per warp
#define ROWS_PER_BLOCK 128        // 8 warps * 16
#define NCH     25                // 24 full 32-k chunks + 16-k tail
#define NBUF    4                 // pipeline depth (prefetch distance 3)
#define XP      36                // stage pitch: bank=(4g+tig+kl)%32 -> conflict-free
#define STGF    (WROWS * XP)      // 576 floats per stage buffer
#define BTP     788               // Bt pitch: 788%32=20 -> banks 20g+tig distinct

// dynamic smem (floats)
#define SM_BT     0                              // 10 x 788 = 7880
#define SM_CF     7880                           // 10
#define SM_STG    7904                           // 8 warps * 4 bufs * 576
#define SM_TOTALF (SM_STG + 8 * NBUF * STGF)     // 26336 floats = 105344 B

typedef unsigned long long u64;

__device__ float g_Mf[KDIM * NOUT];   // tf32-rounded collapsed matrix [k][j]
__device__ float g_cf[NOUT];          // fp32 collapsed bias

// ---- helpers ---------------------------------------------------------------
__device__ __forceinline__ uint32_t cvt_tf32(float f) {
    uint32_t u;
    asm("cvt.rna.tf32.f32 %0, %1;" : "=r"(u) : "f"(f));
    return u;
}
__device__ __forceinline__ void mma_tf32(float& d0, float& d1, float& d2, float& d3,
                                         uint32_t a0, uint32_t a1, uint32_t a2, uint32_t a3,
                                         uint32_t b0, uint32_t b1) {
    asm volatile(
        "mma.sync.aligned.m16n8k8.row.col.f32.tf32.tf32.f32 "
        "{%0,%1,%2,%3}, {%4,%5,%6,%7}, {%8,%9}, {%0,%1,%2,%3};"
        : "+f"(d0), "+f"(d1), "+f"(d2), "+f"(d3)
        : "r"(a0), "r"(a1), "r"(a2), "r"(a3), "r"(b0), "r"(b1));
}
__device__ __forceinline__ void cp16(unsigned dst, const float* src) {
    asm volatile("cp.async.cg.shared.global [%0], [%1], 16;" :: "r"(dst), "l"(src));
}
#define CP_COMMIT() asm volatile("cp.async.commit_group;" ::: "memory")
#define CP_WAIT3()  asm volatile("cp.async.wait_group 3;" ::: "memory")

// ---------------------------------------------------------------------------
// collapse_all: 31 blocks x 256 (proven), tf32-rounds Mf on store.
// ---------------------------------------------------------------------------
#define SW1   0
#define SW2   2144
#define SW3   2464
#define SB0   3072
#define SB1   3152
#define SBS   3184
#define SWTOT 3264

__global__ void collapse_all(const float* __restrict__ W0, const float* __restrict__ b0,
                             const float* __restrict__ W1, const float* __restrict__ b1,
                             const float* __restrict__ W2, const float* __restrict__ b2,
                             const float* __restrict__ W3, const float* __restrict__ b3,
                             const float* __restrict__ W4, const float* __restrict__ b4,
                             const float* __restrict__ W5, const float* __restrict__ b5,
                             const float* __restrict__ W6, const float* __restrict__ b6,
                             const float* __restrict__ W7, const float* __restrict__ b7,
                             const float* __restrict__ W8, const float* __restrict__ b8) {
    __shared__ float sw[SWTOT];
    __shared__ float R[2][100];
    __shared__ float Q[31 * 10];
    __shared__ float S[69 * 10];
    __shared__ float c1s[31];
    __shared__ float cs[2][10];
    const int t = threadIdx.x;

    for (int i = t; i < 2139; i += CTPB) sw[SW1 + i] = W1[i];
    for (int i = t; i < 310;  i += CTPB) sw[SW2 + i] = W2[i];
    {   const float* Wsrc[6] = {W3, W4, W5, W6, W7, W8};
        for (int i = t; i < 600; i += CTPB) sw[SW3 + i] = Wsrc[i / 100][i % 100];
    }
    if (t < 69)  sw[SB0 + t] = b0[t];
    if (t < 31)  sw[SB1 + t] = b1[t];
    {   const float* bsrc[7] = {b2, b3, b4, b5, b6, b7, b8};
        if (t < 70) sw[SBS + t] = bsrc[t / 10][t % 10];
    }
    __syncthreads();

    if (t < 100) R[0][t] = sw[SW3 + (t % 10) * 10 + (t / 10)];
    __syncthreads();
    int cur = 0;
    #pragma unroll 1
    for (int l = 1; l < 6; ++l) {
        int nxt = cur ^ 1;
        if (t < 100) {
            int k = t / 10, j = t % 10;
            float s = 0.f;
            #pragma unroll
            for (int m = 0; m < 10; ++m)
                s = fmaf(R[cur][k * 10 + m], sw[SW3 + l * 100 + j * 10 + m], s);
            R[nxt][t] = s;
        }
        __syncthreads();
        cur = nxt;
    }

    for (int e = t; e < 310; e += CTPB) {
        int k = e / 10, j = e % 10;
        float s = 0.f;
        #pragma unroll
        for (int m = 0; m < 10; ++m)
            s = fmaf(sw[SW2 + m * 31 + k], R[cur][m * 10 + j], s);
        Q[e] = s;
    }
    __syncthreads();

    for (int e = t; e < 690; e += CTPB) {
        int k = e / 10, j = e % 10;
        float s0 = 0.f, s1 = 0.f, s2 = 0.f, s3 = 0.f;
        #pragma unroll
        for (int m = 0; m < 28; m += 4) {
            s0 = fmaf(sw[SW1 + (m + 0) * 69 + k], Q[(m + 0) * 10 + j], s0);
            s1 = fmaf(sw[SW1 + (m + 1) * 69 + k], Q[(m + 1) * 10 + j], s1);
            s2 = fmaf(sw[SW1 + (m + 2) * 69 + k], Q[(m + 2) * 10 + j], s2);
            s3 = fmaf(sw[SW1 + (m + 3) * 69 + k], Q[(m + 3) * 10 + j], s3);
        }
        #pragma unroll
        for (int m = 28; m < 31; ++m)
            s0 = fmaf(sw[SW1 + m * 69 + k], Q[m * 10 + j], s0);
        S[e] = (s0 + s1) + (s2 + s3);
    }
    __syncthreads();

    {
        int e = blockIdx.x * CTPB + t;
        if (e < KDIM * NOUT) {
            int j = e / KDIM, i = e % KDIM;
            float s0 = 0.f, s1 = 0.f, s2 = 0.f, s3 = 0.f;
            #pragma unroll
            for (int k = 0; k < 68; k += 4) {
                s0 = fmaf(W0[(k + 0) * KDIM + i], S[(k + 0) * 10 + j], s0);
                s1 = fmaf(W0[(k + 1) * KDIM + i], S[(k + 1) * 10 + j], s1);
                s2 = fmaf(W0[(k + 2) * KDIM + i], S[(k + 2) * 10 + j], s2);
                s3 = fmaf(W0[(k + 3) * KDIM + i], S[(k + 3) * 10 + j], s3);
            }
            s0 = fmaf(W0[68 * KDIM + i], S[68 * 10 + j], s0);
            float v = (s0 + s1) + (s2 + s3);
            g_Mf[i * 10 + j] = __uint_as_float(cvt_tf32(v));   // pre-round to tf32
        }
    }

    if (blockIdx.x == 0) {
        if (t < 31) {
            float s = sw[SB1 + t];
            for (int k = 0; k < 69; ++k)
                s = fmaf(sw[SB0 + k], sw[SW1 + t * 69 + k], s);
            c1s[t] = s;
        }
        __syncthreads();
        if (t < 10) {
            float s = sw[SBS + t];
            for (int m = 0; m < 31; ++m)
                s = fmaf(c1s[m], sw[SW2 + t * 31 + m], s);
            cs[0][t] = s;
        }
        __syncthreads();
        int cb = 0;
        #pragma unroll 1
        for (int l = 0; l < 6; ++l) {
            int nb = cb ^ 1;
            if (t < 10) {
                float s = sw[SBS + (l + 1) * 10 + t];
                #pragma unroll
                for (int m = 0; m < 10; ++m)
                    s = fmaf(cs[cb][m], sw[SW3 + l * 100 + t * 10 + m], s);
                cs[nb][t] = s;
            }
            __syncthreads();
            cb = nb;
        }
        if (t < 10) g_cf[t] = cs[cb][t];
    }
}

// ---------------------------------------------------------------------------
// mlp_mma: out = x @ Mf + cf via m16n8k8 tf32 mma.sync.
//  4-deep warp-private cp.async pipeline over 32-k chunks.
// ---------------------------------------------------------------------------

// stage one full 32-k chunk (16 rows x 32 floats) of this warp's x slab
__device__ __forceinline__ void stage32(unsigned dst, const float* gsrc, int lane) {
    #pragma unroll
    for (int i = 0; i < 4; ++i) {
        int f4 = lane + 32 * i;                 // 0..127 granules of 16B
        int row = f4 >> 3, col = (f4 & 7) << 2;
        cp16(dst + (row * XP + col) * 4, gsrc + row * KDIM + col);
    }
}
// stage the 16-k tail (16 rows x 16 floats)
__device__ __forceinline__ void stage16(unsigned dst, const float* gsrc, int lane) {
    #pragma unroll
    for (int i = 0; i < 2; ++i) {
        int f4 = lane + 32 * i;                 // 0..63
        int row = f4 >> 2, col = (f4 & 3) << 2;
        cp16(dst + (row * XP + col) * 4, gsrc + row * KDIM + col);
    }
}

__global__ __launch_bounds__(MTPB, 2)
void mlp_mma(const float* __restrict__ x, float* __restrict__ out) {
    extern __shared__ float sm[];
    float* Bt  = sm + SM_BT;     // Bt[j*788 + k] (tf32 bits)
    float* cfs = sm + SM_CF;

    const int t    = threadIdx.x;
    const int lane = t & 31;
    const int warp = t >> 5;
    const int g    = lane >> 2;     // 0..7
    const int tig  = lane & 3;      // 0..3

    float* stg[NBUF];
    unsigned stg_u32[NBUF];
    #pragma unroll
    for (int b = 0; b < NBUF; ++b) {
        stg[b] = sm + SM_STG + (warp * NBUF + b) * STGF;
        stg_u32[b] = (unsigned)__cvta_generic_to_shared(stg[b]);
    }

    const int wrow = blockIdx.x * ROWS_PER_BLOCK + warp * WROWS;
    const float* xw = x + (size_t)wrow * KDIM;

    // ---- prologue: stage chunks 0,1,2 (3 committed groups) ----
    stage32(stg_u32[0], xw,       lane); CP_COMMIT();
    stage32(stg_u32[1], xw + 32,  lane); CP_COMMIT();
    stage32(stg_u32[2], xw + 64,  lane); CP_COMMIT();

    // ---- fill Bt (coalesced g_Mf read, scatter to smem) + bias ----
    for (int i = t; i < KDIM * NOUT; i += MTPB) {
        int k = i / 10, j = i % 10;
        Bt[j * BTP + k] = g_Mf[i];
    }
    if (t < NOUT) cfs[t] = g_cf[t];
    __syncthreads();

    float d0[4] = {0.f, 0.f, 0.f, 0.f};   // j 0..7
    float d1[4] = {0.f, 0.f, 0.f, 0.f};   // j 8,9 (in 8-wide half)

    const float* bg0 = Bt + g * BTP;            // n-half 0 row for this lane
    const float* bg1 = Bt + (8 + (g & 1)) * BTP; // n-half 1 (only g<2 used)

    #pragma unroll 1
    for (int ch = 0; ch < NCH; ++ch) {
        // prefetch chunk ch+3 (distance 3); empty commit keeps group counting
        if (ch + 3 < NCH - 1)
            stage32(stg_u32[(ch + 3) & 3], xw + (ch + 3) * 32, lane);
        else if (ch + 3 == NCH - 1)
            stage16(stg_u32[(ch + 3) & 3], xw + (NCH - 1) * 32, lane);
        CP_COMMIT();
        CP_WAIT3();                            // chunk ch resident
        __syncwarp();

        const float* xs = stg[ch & 3];
        const int nsteps = (ch == NCH - 1) ? 2 : 4;
        #pragma unroll
        for (int st = 0; st < 4; ++st) {
            if (st >= nsteps) break;
            const int kl = st * 8;
            const int kg = ch * 32 + kl;

            uint32_t a0 = cvt_tf32(xs[(g    ) * XP + kl + tig    ]);
            uint32_t a1 = cvt_tf32(xs[(g + 8) * XP + kl + tig    ]);
            uint32_t a2 = cvt_tf32(xs[(g    ) * XP + kl + tig + 4]);
            uint32_t a3 = cvt_tf32(xs[(g + 8) * XP + kl + tig + 4]);

            // conflict-free B loads from transposed layout
            uint32_t b00 = __float_as_uint(bg0[kg + tig    ]);
            uint32_t b01 = __float_as_uint(bg0[kg + tig + 4]);
            mma_tf32(d0[0], d0[1], d0[2], d0[3], a0, a1, a2, a3, b00, b01);

            uint32_t b10 = (g < 2) ? __float_as_uint(bg1[kg + tig    ]) : 0u;
            uint32_t b11 = (g < 2) ? __float_as_uint(bg1[kg + tig + 4]) : 0u;
            mma_tf32(d1[0], d1[1], d1[2], d1[3], a0, a1, a2, a3, b10, b11);
        }
        __syncwarp();                          // buffer reuse fence
    }

    // ---- epilogue: D c0,c1 -> (row g, cols 2tig,2tig+1); c2,c3 -> row g+8 ----
    {
        const int j0 = 2 * tig;
        float2 v;
        float* opA = out + (size_t)(wrow + g) * NOUT;
        float* opB = out + (size_t)(wrow + g + 8) * NOUT;
        v.x = d0[0] + cfs[j0];     v.y = d0[1] + cfs[j0 + 1];
        *(float2*)(opA + j0) = v;
        v.x = d0[2] + cfs[j0];     v.y = d0[3] + cfs[j0 + 1];
        *(float2*)(opB + j0) = v;
        if (tig == 0) {                        // j = 8,9
            v.x = d1[0] + cfs[8];  v.y = d1[1] + cfs[9];
            *(float2*)(opA + 8) = v;
            v.x = d1[2] + cfs[8];  v.y = d1[3] + cfs[9];
            *(float2*)(opB + 8) = v;
        }
    }
}

// ---------------------------------------------------------------------------
extern "C" void kernel_launch(void* const* d_in, const int* in_sizes, int n_in,
                              void* d_out, int out_size) {
    const float* x  = (const float*)d_in[0];
    const float* W0 = (const float*)d_in[1];
    const float* b0 = (const float*)d_in[2];
    const float* W1 = (const float*)d_in[3];
    const float* b1 = (const float*)d_in[4];
    const float* W2 = (const float*)d_in[5];
    const float* b2 = (const float*)d_in[6];
    const float* W3 = (const float*)d_in[7];
    const float* b3 = (const float*)d_in[8];
    const float* W4 = (const float*)d_in[9];
    const float* b4 = (const float*)d_in[10];
    const float* W5 = (const float*)d_in[11];
    const float* b5 = (const float*)d_in[12];
    const float* W6 = (const float*)d_in[13];
    const float* b6 = (const float*)d_in[14];
    const float* W7 = (const float*)d_in[15];
    const float* b7 = (const float*)d_in[16];
    const float* W8 = (const float*)d_in[17];
    const float* b8 = (const float*)d_in[18];
    float* out = (float*)d_out;

    static bool attr_set = false;
    const int smem_bytes = SM_TOTALF * sizeof(float);    // 105344 B
    if (!attr_set) {
        cudaFuncSetAttribute(mlp_mma, cudaFuncAttributeMaxDynamicSharedMemorySize,
                             smem_bytes);
        attr_set = true;
    }

    collapse_all<<<(KDIM * NOUT + CTPB - 1) / CTPB, CTPB>>>(
        W0, b0, W1, b1, W2, b2, W3, b3, W4, b4,
        W5, b5, W6, b6, W7, b7, W8, b8);

    mlp_mma<<<BSZ / ROWS_PER_BLOCK, MTPB, smem_bytes>>>(x, out);   // 512 blocks
}

// round 14
// speedup vs baseline: 1.0367x; 1.0367x over previous
#include <cuda_runtime.h>
#include <cuda_bf16.h>
#include <cstdint>

// ---------------------------------------------------------------------------
// y = x @ Mf + cf  (exact collapse of the 9-layer linear chain), main pass on
// tensor cores via mma.sync.m16n8k8 tf32.
// R14: x staged with cp.async.bulk (one 384B bulk copy per row-segment,
// mbarrier complete_tx) -> staging issue cost ~25x lower than 16B cp.async;
// 96-k chunks, depth 2, prefetch distance 2. B (tf32 Mf^T) lives in global,
// cached in L1, freeing smem so 2 blocks/SM still fit.
// ---------------------------------------------------------------------------

#define BSZ     65536
#define KDIM    784
#define NOUT    10
#define CTPB    256
#define MTPB    256               // 8 warps
#define WROWS   16                // rows per warp
#define ROWS_PER_BLOCK 128        // 8 warps * 16
#define CHUNK   96                // k per chunk (floats)
#define NCH     9                 // 8 full 96-k chunks + 16-k tail
#define XP      100               // stage pitch: 100%32=4 -> (4g+tig) conflict-free
#define STGF    (WROWS * XP)      // 1600 floats per stage buffer
#define SM_TOTALF (8 * 2 * STGF)  // 25600 floats = 102400 B dynamic smem

typedef unsigned long long u64;

__device__ float g_Bt[NOUT * KDIM];   // tf32-rounded Mf^T: g_Bt[j*784 + k]
__device__ float g_cf[NOUT];          // fp32 collapsed bias

// ---- helpers ---------------------------------------------------------------
__device__ __forceinline__ uint32_t cvt_tf32(float f) {
    uint32_t u;
    asm("cvt.rna.tf32.f32 %0, %1;" : "=r"(u) : "f"(f));
    return u;
}
__device__ __forceinline__ void mma_tf32(float& d0, float& d1, float& d2, float& d3,
                                         uint32_t a0, uint32_t a1, uint32_t a2, uint32_t a3,
                                         uint32_t b0, uint32_t b1) {
    asm volatile(
        "mma.sync.aligned.m16n8k8.row.col.f32.tf32.tf32.f32 "
        "{%0,%1,%2,%3}, {%4,%5,%6,%7}, {%8,%9}, {%0,%1,%2,%3};"
        : "+f"(d0), "+f"(d1), "+f"(d2), "+f"(d3)
        : "r"(a0), "r"(a1), "r"(a2), "r"(a3), "r"(b0), "r"(b1));
}
__device__ __forceinline__ void bulk_cp(unsigned dst, const void* src,
                                        unsigned bytes, unsigned mbar) {
    asm volatile(
        "cp.async.bulk.shared::cta.global.mbarrier::complete_tx::bytes "
        "[%0], [%1], %2, [%3];"
        :: "r"(dst), "l"(src), "r"(bytes), "r"(mbar) : "memory");
}
#define MBAR_INIT(a, c) asm volatile("mbarrier.init.shared.b64 [%0], %1;" :: "r"(a), "r"(c) : "memory")
#define MBAR_EXPECT(a, b) asm volatile("mbarrier.arrive.expect_tx.shared.b64 _, [%0], %1;" :: "r"(a), "r"(b) : "memory")
__device__ __forceinline__ void mbar_wait(uint32_t mbar, uint32_t parity) {
    asm volatile(
        "{\n\t.reg .pred P1;\n\t"
        "WL_%=:\n\t"
        "mbarrier.try_wait.parity.acquire.cta.shared::cta.b64 P1, [%0], %1, 0x989680;\n\t"
        "@P1 bra.uni WD_%=;\n\t"
        "bra.uni WL_%=;\n\t"
        "WD_%=:\n\t}"
        :: "r"(mbar), "r"(parity) : "memory");
}

// ---------------------------------------------------------------------------
// collapse_all: 31 blocks x 256 (proven); stores Bt[j*784+k] (tf32-rounded).
// ---------------------------------------------------------------------------
#define SW1   0
#define SW2   2144
#define SW3   2464
#define SB0   3072
#define SB1   3152
#define SBS   3184
#define SWTOT 3264

__global__ void collapse_all(const float* __restrict__ W0, const float* __restrict__ b0,
                             const float* __restrict__ W1, const float* __restrict__ b1,
                             const float* __restrict__ W2, const float* __restrict__ b2,
                             const float* __restrict__ W3, const float* __restrict__ b3,
                             const float* __restrict__ W4, const float* __restrict__ b4,
                             const float* __restrict__ W5, const float* __restrict__ b5,
                             const float* __restrict__ W6, const float* __restrict__ b6,
                             const float* __restrict__ W7, const float* __restrict__ b7,
                             const float* __restrict__ W8, const float* __restrict__ b8) {
    __shared__ float sw[SWTOT];
    __shared__ float R[2][100];
    __shared__ float Q[31 * 10];
    __shared__ float S[69 * 10];
    __shared__ float c1s[31];
    __shared__ float cs[2][10];
    const int t = threadIdx.x;

    for (int i = t; i < 2139; i += CTPB) sw[SW1 + i] = W1[i];
    for (int i = t; i < 310;  i += CTPB) sw[SW2 + i] = W2[i];
    {   const float* Wsrc[6] = {W3, W4, W5, W6, W7, W8};
        for (int i = t; i < 600; i += CTPB) sw[SW3 + i] = Wsrc[i / 100][i % 100];
    }
    if (t < 69)  sw[SB0 + t] = b0[t];
    if (t < 31)  sw[SB1 + t] = b1[t];
    {   const float* bsrc[7] = {b2, b3, b4, b5, b6, b7, b8};
        if (t < 70) sw[SBS + t] = bsrc[t / 10][t % 10];
    }
    __syncthreads();

    if (t < 100) R[0][t] = sw[SW3 + (t % 10) * 10 + (t / 10)];
    __syncthreads();
    int cur = 0;
    #pragma unroll 1
    for (int l = 1; l < 6; ++l) {
        int nxt = cur ^ 1;
        if (t < 100) {
            int k = t / 10, j = t % 10;
            float s = 0.f;
            #pragma unroll
            for (int m = 0; m < 10; ++m)
                s = fmaf(R[cur][k * 10 + m], sw[SW3 + l * 100 + j * 10 + m], s);
            R[nxt][t] = s;
        }
        __syncthreads();
        cur = nxt;
    }

    for (int e = t; e < 310; e += CTPB) {
        int k = e / 10, j = e % 10;
        float s = 0.f;
        #pragma unroll
        for (int m = 0; m < 10; ++m)
            s = fmaf(sw[SW2 + m * 31 + k], R[cur][m * 10 + j], s);
        Q[e] = s;
    }
    __syncthreads();

    for (int e = t; e < 690; e += CTPB) {
        int k = e / 10, j = e % 10;
        float s0 = 0.f, s1 = 0.f, s2 = 0.f, s3 = 0.f;
        #pragma unroll
        for (int m = 0; m < 28; m += 4) {
            s0 = fmaf(sw[SW1 + (m + 0) * 69 + k], Q[(m + 0) * 10 + j], s0);
            s1 = fmaf(sw[SW1 + (m + 1) * 69 + k], Q[(m + 1) * 10 + j], s1);
            s2 = fmaf(sw[SW1 + (m + 2) * 69 + k], Q[(m + 2) * 10 + j], s2);
            s3 = fmaf(sw[SW1 + (m + 3) * 69 + k], Q[(m + 3) * 10 + j], s3);
        }
        #pragma unroll
        for (int m = 28; m < 31; ++m)
            s0 = fmaf(sw[SW1 + m * 69 + k], Q[m * 10 + j], s0);
        S[e] = (s0 + s1) + (s2 + s3);
    }
    __syncthreads();

    {
        int e = blockIdx.x * CTPB + t;
        if (e < KDIM * NOUT) {
            int j = e / KDIM, i = e % KDIM;     // consecutive t -> coalesced W0 & Bt
            float s0 = 0.f, s1 = 0.f, s2 = 0.f, s3 = 0.f;
            #pragma unroll
            for (int k = 0; k < 68; k += 4) {
                s0 = fmaf(W0[(k + 0) * KDIM + i], S[(k + 0) * 10 + j], s0);
                s1 = fmaf(W0[(k + 1) * KDIM + i], S[(k + 1) * 10 + j], s1);
                s2 = fmaf(W0[(k + 2) * KDIM + i], S[(k + 2) * 10 + j], s2);
                s3 = fmaf(W0[(k + 3) * KDIM + i], S[(k + 3) * 10 + j], s3);
            }
            s0 = fmaf(W0[68 * KDIM + i], S[68 * 10 + j], s0);
            float v = (s0 + s1) + (s2 + s3);
            g_Bt[j * KDIM + i] = __uint_as_float(cvt_tf32(v));  // transposed + rounded
        }
    }

    if (blockIdx.x == 0) {
        if (t < 31) {
            float s = sw[SB1 + t];
            for (int k = 0; k < 69; ++k)
                s = fmaf(sw[SB0 + k], sw[SW1 + t * 69 + k], s);
            c1s[t] = s;
        }
        __syncthreads();
        if (t < 10) {
            float s = sw[SBS + t];
            for (int m = 0; m < 31; ++m)
                s = fmaf(c1s[m], sw[SW2 + t * 31 + m], s);
            cs[0][t] = s;
        }
        __syncthreads();
        int cb = 0;
        #pragma unroll 1
        for (int l = 0; l < 6; ++l) {
            int nb = cb ^ 1;
            if (t < 10) {
                float s = sw[SBS + (l + 1) * 10 + t];
                #pragma unroll
                for (int m = 0; m < 10; ++m)
                    s = fmaf(cs[cb][m], sw[SW3 + l * 100 + t * 10 + m], s);
                cs[nb][t] = s;
            }
            __syncthreads();
            cb = nb;
        }
        if (t < 10) g_cf[t] = cs[cb][t];
    }
}

// ---------------------------------------------------------------------------
// mlp_mma: out = x @ Mf + cf via m16n8k8 tf32 mma.sync.
//  96-k chunks staged with cp.async.bulk (lane 0 issues 16 row copies per
//  chunk), warp-private mbarrier per buffer, prefetch distance 2.
// ---------------------------------------------------------------------------
__global__ __launch_bounds__(MTPB, 2)
void mlp_mma(const float* __restrict__ x, float* __restrict__ out) {
    extern __shared__ float sm[];
    __shared__ float cfs[NOUT];
    __shared__ __align__(8) u64 mbars[8][2];

    const int t    = threadIdx.x;
    const int lane = t & 31;
    const int warp = t >> 5;
    const int g    = lane >> 2;     // 0..7
    const int tig  = lane & 3;      // 0..3

    float* stg[2];
    unsigned stg_u32[2], mb_u32[2];
    #pragma unroll
    for (int b = 0; b < 2; ++b) {
        stg[b] = sm + (warp * 2 + b) * STGF;
        stg_u32[b] = (unsigned)__cvta_generic_to_shared(stg[b]);
        mb_u32[b]  = (unsigned)__cvta_generic_to_shared(&mbars[warp][b]);
    }

    const int wrow = blockIdx.x * ROWS_PER_BLOCK + warp * WROWS;
    const float* xw = x + (size_t)wrow * KDIM;

    // ---- init mbars + stage chunks 0,1 ----
    if (lane == 0) {
        MBAR_INIT(mb_u32[0], 1);
        MBAR_INIT(mb_u32[1], 1);
    }
    __syncwarp();
    if (lane == 0) {
        #pragma unroll
        for (int b = 0; b < 2; ++b) {
            MBAR_EXPECT(mb_u32[b], WROWS * CHUNK * 4);
            #pragma unroll
            for (int r = 0; r < WROWS; ++r)
                bulk_cp(stg_u32[b] + (r * XP) * 4,
                        xw + (size_t)r * KDIM + b * CHUNK,
                        CHUNK * 4, mb_u32[b]);
        }
    }

    if (t < NOUT) cfs[t] = g_cf[t];
    __syncthreads();

    float d0[4] = {0.f, 0.f, 0.f, 0.f};   // j 0..7
    float d1[4] = {0.f, 0.f, 0.f, 0.f};   // j 8,9

    const float* bg0 = g_Bt + g * KDIM;
    const float* bg1 = g_Bt + (8 + (g & 1)) * KDIM;

    #pragma unroll 1
    for (int ch = 0; ch < NCH; ++ch) {
        mbar_wait(mb_u32[ch & 1], (ch >> 1) & 1);   // chunk ch resident

        const float* xs = stg[ch & 1];
        const int nsteps = (ch == NCH - 1) ? 2 : 12;
        #pragma unroll 4
        for (int st = 0; st < nsteps; ++st) {
            const int kl = st * 8;
            const int kg = ch * CHUNK + kl;

            uint32_t a0 = cvt_tf32(xs[(g    ) * XP + kl + tig    ]);
            uint32_t a1 = cvt_tf32(xs[(g + 8) * XP + kl + tig    ]);
            uint32_t a2 = cvt_tf32(xs[(g    ) * XP + kl + tig + 4]);
            uint32_t a3 = cvt_tf32(xs[(g + 8) * XP + kl + tig + 4]);

            uint32_t b00 = __float_as_uint(__ldg(bg0 + kg + tig    ));
            uint32_t b01 = __float_as_uint(__ldg(bg0 + kg + tig + 4));
            mma_tf32(d0[0], d0[1], d0[2], d0[3], a0, a1, a2, a3, b00, b01);

            uint32_t b10 = (g < 2) ? __float_as_uint(__ldg(bg1 + kg + tig    )) : 0u;
            uint32_t b11 = (g < 2) ? __float_as_uint(__ldg(bg1 + kg + tig + 4)) : 0u;
            mma_tf32(d1[0], d1[1], d1[2], d1[3], a0, a1, a2, a3, b10, b11);
        }
        __syncwarp();                                // all lanes done with buffer

        // stage chunk ch+2 into the just-freed buffer (prefetch distance 2)
        if (ch + 2 < NCH && lane == 0) {
            const int c = ch + 2;
            const unsigned bytes = (c == NCH - 1) ? 16 * 4 : CHUNK * 4;
            MBAR_EXPECT(mb_u32[ch & 1], WROWS * bytes);
            #pragma unroll
            for (int r = 0; r < WROWS; ++r)
                bulk_cp(stg_u32[ch & 1] + (r * XP) * 4,
                        xw + (size_t)r * KDIM + c * CHUNK,
                        bytes, mb_u32[ch & 1]);
        }
    }

    // ---- epilogue: D c0,c1 -> (row g, cols 2tig,2tig+1); c2,c3 -> row g+8 ----
    {
        const int j0 = 2 * tig;
        float2 v;
        float* opA = out + (size_t)(wrow + g) * NOUT;
        float* opB = out + (size_t)(wrow + g + 8) * NOUT;
        v.x = d0[0] + cfs[j0];     v.y = d0[1] + cfs[j0 + 1];
        *(float2*)(opA + j0) = v;
        v.x = d0[2] + cfs[j0];     v.y = d0[3] + cfs[j0 + 1];
        *(float2*)(opB + j0) = v;
        if (tig == 0) {                        // j = 8,9
            v.x = d1[0] + cfs[8];  v.y = d1[1] + cfs[9];
            *(float2*)(opA + 8) = v;
            v.x = d1[2] + cfs[8];  v.y = d1[3] + cfs[9];
            *(float2*)(opB + 8) = v;
        }
    }
}

// ---------------------------------------------------------------------------
extern "C" void kernel_launch(void* const* d_in, const int* in_sizes, int n_in,
                              void* d_out, int out_size) {
    const float* x  = (const float*)d_in[0];
    const float* W0 = (const float*)d_in[1];
    const float* b0 = (const float*)d_in[2];
    const float* W1 = (const float*)d_in[3];
    const float* b1 = (const float*)d_in[4];
    const float* W2 = (const float*)d_in[5];
    const float* b2 = (const float*)d_in[6];
    const float* W3 = (const float*)d_in[7];
    const float* b3 = (const float*)d_in[8];
    const float* W4 = (const float*)d_in[9];
    const float* b4 = (const float*)d_in[10];
    const float* W5 = (const float*)d_in[11];
    const float* b5 = (const float*)d_in[12];
    const float* W6 = (const float*)d_in[13];
    const float* b6 = (const float*)d_in[14];
    const float* W7 = (const float*)d_in[15];
    const float* b7 = (const float*)d_in[16];
    const float* W8 = (const float*)d_in[17];
    const float* b8 = (const float*)d_in[18];
    float* out = (float*)d_out;

    static bool attr_set = false;
    const int smem_bytes = SM_TOTALF * sizeof(float);    // 102400 B
    if (!attr_set) {
        cudaFuncSetAttribute(mlp_mma, cudaFuncAttributeMaxDynamicSharedMemorySize,
                             smem_bytes);
        attr_set = true;
    }

    collapse_all<<<(KDIM * NOUT + CTPB - 1) / CTPB, CTPB>>>(
        W0, b0, W1, b1, W2, b2, W3, b3, W4, b4,
        W5, b5, W6, b6, W7, b7, W8, b8);

    mlp_mma<<<BSZ / ROWS_PER_BLOCK, MTPB, smem_bytes>>>(x, out);   // 512 blocks
}

// round 15
// speedup vs baseline: 1.1159x; 1.0764x over previous
#include <cuda_runtime.h>
#include <cuda_bf16.h>
#include <cstdint>

// ---------------------------------------------------------------------------
// y = x @ Mf + cf  (exact collapse of the 9-layer linear chain), main pass on
// tensor cores via mma.sync.m16n8k8 tf32.
// R15: B evicted from smem into lane-packed global arrays (one coalesced
// LDG.64 per step, L2-resident); freed smem funds a depth-3 cp.async pipeline
// (64-k chunks, prefetch distance 2) -> staging latency fully covered.
// ---------------------------------------------------------------------------

#define BSZ     65536
#define KDIM    784
#define NOUT    10
#define CTPB    256
#define MTPB    256               // 8 warps
#define WROWS   16                // rows per warp
#define ROWS_PER_BLOCK 128        // 8 warps * 16
#define CHUNK   64                // k per chunk
#define NCH     13                // 12 full 64-k chunks + 16-k tail
#define NBUF    3                 // prefetch distance 2
#define NSTEP   98                // total k-steps of 8
#define XP      68                // stage pitch: (4g+tig) banks distinct
#define STGF    (WROWS * XP)      // 1088 floats per stage buffer
#define SM_TOTALF (8 * NBUF * STGF)   // 26112 floats = 104448 B

typedef unsigned long long u64;

__device__ float2 g_Bp0[NSTEP * 32];  // lane-packed B frag, n-half 0 (tf32 bits)
__device__ float2 g_Bp1[NSTEP * 32];  // n-half 1 (j=8,9; zero for lanes g>=2)
__device__ float  g_cf[NOUT];         // fp32 collapsed bias

// ---- helpers ---------------------------------------------------------------
__device__ __forceinline__ uint32_t cvt_tf32(float f) {
    uint32_t u;
    asm("cvt.rna.tf32.f32 %0, %1;" : "=r"(u) : "f"(f));
    return u;
}
__device__ __forceinline__ void mma_tf32(float& d0, float& d1, float& d2, float& d3,
                                         uint32_t a0, uint32_t a1, uint32_t a2, uint32_t a3,
                                         uint32_t b0, uint32_t b1) {
    asm volatile(
        "mma.sync.aligned.m16n8k8.row.col.f32.tf32.tf32.f32 "
        "{%0,%1,%2,%3}, {%4,%5,%6,%7}, {%8,%9}, {%0,%1,%2,%3};"
        : "+f"(d0), "+f"(d1), "+f"(d2), "+f"(d3)
        : "r"(a0), "r"(a1), "r"(a2), "r"(a3), "r"(b0), "r"(b1));
}
__device__ __forceinline__ void cp16(unsigned dst, const float* src) {
    asm volatile("cp.async.cg.shared.global [%0], [%1], 16;" :: "r"(dst), "l"(src));
}
#define CP_COMMIT() asm volatile("cp.async.commit_group;" ::: "memory")
#define CP_WAIT2()  asm volatile("cp.async.wait_group 2;" ::: "memory")

// stage 16 rows x 64 floats (16 granules/row, 8 per lane)
__device__ __forceinline__ void stage64(unsigned dst, const float* gsrc, int lane) {
    #pragma unroll
    for (int i = 0; i < 8; ++i) {
        int f4 = lane + 32 * i;                 // 0..255
        int row = f4 >> 4, col = (f4 & 15) << 2;
        cp16(dst + (row * XP + col) * 4, gsrc + row * KDIM + col);
    }
}
// stage the 16-k tail (16 rows x 16 floats)
__device__ __forceinline__ void stage16(unsigned dst, const float* gsrc, int lane) {
    #pragma unroll
    for (int i = 0; i < 2; ++i) {
        int f4 = lane + 32 * i;                 // 0..63
        int row = f4 >> 2, col = (f4 & 3) << 2;
        cp16(dst + (row * XP + col) * 4, gsrc + row * KDIM + col);
    }
}

// ---------------------------------------------------------------------------
// collapse_all: 31 blocks x 256 (proven chain); scatters Mf into the
// lane-packed B arrays (tf32-rounded); block 0 zero-fills unused pair1 lanes
// and folds the bias.
// ---------------------------------------------------------------------------
#define SW1   0
#define SW2   2144
#define SW3   2464
#define SB0   3072
#define SB1   3152
#define SBS   3184
#define SWTOT 3264

__global__ void collapse_all(const float* __restrict__ W0, const float* __restrict__ b0,
                             const float* __restrict__ W1, const float* __restrict__ b1,
                             const float* __restrict__ W2, const float* __restrict__ b2,
                             const float* __restrict__ W3, const float* __restrict__ b3,
                             const float* __restrict__ W4, const float* __restrict__ b4,
                             const float* __restrict__ W5, const float* __restrict__ b5,
                             const float* __restrict__ W6, const float* __restrict__ b6,
                             const float* __restrict__ W7, const float* __restrict__ b7,
                             const float* __restrict__ W8, const float* __restrict__ b8) {
    __shared__ float sw[SWTOT];
    __shared__ float R[2][100];
    __shared__ float Q[31 * 10];
    __shared__ float S[69 * 10];
    __shared__ float c1s[31];
    __shared__ float cs[2][10];
    const int t = threadIdx.x;

    // zero-fill pair1 lanes 8..31 (block 0 only; disjoint from all scatters)
    if (blockIdx.x == 0) {
        float* p1 = (float*)g_Bp1;
        for (int idx = t; idx < NSTEP * 48; idx += CTPB) {
            int sg = idx / 48, rem = idx % 48;
            p1[(sg * 32 + 8) * 2 + rem] = 0.f;
        }
    }

    for (int i = t; i < 2139; i += CTPB) sw[SW1 + i] = W1[i];
    for (int i = t; i < 310;  i += CTPB) sw[SW2 + i] = W2[i];
    {   const float* Wsrc[6] = {W3, W4, W5, W6, W7, W8};
        for (int i = t; i < 600; i += CTPB) sw[SW3 + i] = Wsrc[i / 100][i % 100];
    }
    if (t < 69)  sw[SB0 + t] = b0[t];
    if (t < 31)  sw[SB1 + t] = b1[t];
    {   const float* bsrc[7] = {b2, b3, b4, b5, b6, b7, b8};
        if (t < 70) sw[SBS + t] = bsrc[t / 10][t % 10];
    }
    __syncthreads();

    if (t < 100) R[0][t] = sw[SW3 + (t % 10) * 10 + (t / 10)];
    __syncthreads();
    int cur = 0;
    #pragma unroll 1
    for (int l = 1; l < 6; ++l) {
        int nxt = cur ^ 1;
        if (t < 100) {
            int k = t / 10, j = t % 10;
            float s = 0.f;
            #pragma unroll
            for (int m = 0; m < 10; ++m)
                s = fmaf(R[cur][k * 10 + m], sw[SW3 + l * 100 + j * 10 + m], s);
            R[nxt][t] = s;
        }
        __syncthreads();
        cur = nxt;
    }

    for (int e = t; e < 310; e += CTPB) {
        int k = e / 10, j = e % 10;
        float s = 0.f;
        #pragma unroll
        for (int m = 0; m < 10; ++m)
            s = fmaf(sw[SW2 + m * 31 + k], R[cur][m * 10 + j], s);
        Q[e] = s;
    }
    __syncthreads();

    for (int e = t; e < 690; e += CTPB) {
        int k = e / 10, j = e % 10;
        float s0 = 0.f, s1 = 0.f, s2 = 0.f, s3 = 0.f;
        #pragma unroll
        for (int m = 0; m < 28; m += 4) {
            s0 = fmaf(sw[SW1 + (m + 0) * 69 + k], Q[(m + 0) * 10 + j], s0);
            s1 = fmaf(sw[SW1 + (m + 1) * 69 + k], Q[(m + 1) * 10 + j], s1);
            s2 = fmaf(sw[SW1 + (m + 2) * 69 + k], Q[(m + 2) * 10 + j], s2);
            s3 = fmaf(sw[SW1 + (m + 3) * 69 + k], Q[(m + 3) * 10 + j], s3);
        }
        #pragma unroll
        for (int m = 28; m < 31; ++m)
            s0 = fmaf(sw[SW1 + m * 69 + k], Q[m * 10 + j], s0);
        S[e] = (s0 + s1) + (s2 + s3);
    }
    __syncthreads();

    {
        int e = blockIdx.x * CTPB + t;
        if (e < KDIM * NOUT) {
            int j = e / KDIM, i = e % KDIM;     // consecutive t -> coalesced W0
            float s0 = 0.f, s1 = 0.f, s2 = 0.f, s3 = 0.f;
            #pragma unroll
            for (int k = 0; k < 68; k += 4) {
                s0 = fmaf(W0[(k + 0) * KDIM + i], S[(k + 0) * 10 + j], s0);
                s1 = fmaf(W0[(k + 1) * KDIM + i], S[(k + 1) * 10 + j], s1);
                s2 = fmaf(W0[(k + 2) * KDIM + i], S[(k + 2) * 10 + j], s2);
                s3 = fmaf(W0[(k + 3) * KDIM + i], S[(k + 3) * 10 + j], s3);
            }
            s0 = fmaf(W0[68 * KDIM + i], S[68 * 10 + j], s0);
            float v = __uint_as_float(cvt_tf32((s0 + s1) + (s2 + s3)));

            // scatter into lane-packed fragment arrays
            int sg = i >> 3, kpos = i & 7, tg = kpos & 3, half = kpos >> 2;
            float* dst;
            if (j < 8) dst = (float*)g_Bp0 + (sg * 32 + j * 4 + tg) * 2 + half;
            else       dst = (float*)g_Bp1 + (sg * 32 + (j - 8) * 4 + tg) * 2 + half;
            *dst = v;
        }
    }

    if (blockIdx.x == 0) {
        if (t < 31) {
            float s = sw[SB1 + t];
            for (int k = 0; k < 69; ++k)
                s = fmaf(sw[SB0 + k], sw[SW1 + t * 69 + k], s);
            c1s[t] = s;
        }
        __syncthreads();
        if (t < 10) {
            float s = sw[SBS + t];
            for (int m = 0; m < 31; ++m)
                s = fmaf(c1s[m], sw[SW2 + t * 31 + m], s);
            cs[0][t] = s;
        }
        __syncthreads();
        int cb = 0;
        #pragma unroll 1
        for (int l = 0; l < 6; ++l) {
            int nb = cb ^ 1;
            if (t < 10) {
                float s = sw[SBS + (l + 1) * 10 + t];
                #pragma unroll
                for (int m = 0; m < 10; ++m)
                    s = fmaf(cs[cb][m], sw[SW3 + l * 100 + t * 10 + m], s);
                cs[nb][t] = s;
            }
            __syncthreads();
            cb = nb;
        }
        if (t < 10) g_cf[t] = cs[cb][t];
    }
}

// ---------------------------------------------------------------------------
// mlp_mma: out = x @ Mf + cf via m16n8k8 tf32 mma.sync.
//  depth-3 warp-private cp.async pipeline, 64-k chunks, distance-2 prefetch.
//  B fragments via one coalesced LDG.64 per step from the packed arrays.
// ---------------------------------------------------------------------------
__global__ __launch_bounds__(MTPB, 2)
void mlp_mma(const float* __restrict__ x, float* __restrict__ out) {
    extern __shared__ float sm[];
    __shared__ float cfs[NOUT];

    const int t    = threadIdx.x;
    const int lane = t & 31;
    const int warp = t >> 5;
    const int g    = lane >> 2;     // 0..7
    const int tig  = lane & 3;      // 0..3

    float* stg[NBUF];
    unsigned stg_u32[NBUF];
    #pragma unroll
    for (int b = 0; b < NBUF; ++b) {
        stg[b] = sm + (warp * NBUF + b) * STGF;
        stg_u32[b] = (unsigned)__cvta_generic_to_shared(stg[b]);
    }

    const int wrow = blockIdx.x * ROWS_PER_BLOCK + warp * WROWS;
    const float* xw = x + (size_t)wrow * KDIM;

    // ---- prologue: stage chunks 0, 1 ----
    stage64(stg_u32[0], xw,          lane); CP_COMMIT();
    stage64(stg_u32[1], xw + CHUNK,  lane); CP_COMMIT();

    if (t < NOUT) cfs[t] = g_cf[t];
    __syncthreads();

    float d0[4] = {0.f, 0.f, 0.f, 0.f};   // j 0..7
    float d1[4] = {0.f, 0.f, 0.f, 0.f};   // j 8,9

    const float2* __restrict__ pb0 = g_Bp0 + lane;   // index: step*32
    const float2* __restrict__ pb1 = g_Bp1 + lane;

    #pragma unroll 1
    for (int ch = 0; ch < NCH; ++ch) {
        // prefetch chunk ch+2 (buffer (ch+2)%3 freed after iter ch-1)
        if (ch + 2 < NCH - 1)
            stage64(stg_u32[(ch + 2) % NBUF], xw + (ch + 2) * CHUNK, lane);
        else if (ch + 2 == NCH - 1)
            stage16(stg_u32[(ch + 2) % NBUF], xw + (NCH - 1) * CHUNK, lane);
        CP_COMMIT();                       // empty group beyond tail keeps count
        CP_WAIT2();                        // chunk ch resident
        __syncwarp();

        const float* xs = stg[ch % NBUF];
        const int nsteps = (ch == NCH - 1) ? 2 : 8;
        #pragma unroll 4
        for (int st = 0; st < nsteps; ++st) {
            const int kl = st * 8;
            const int sg = ch * 8 + st;    // global step

            uint32_t a0 = cvt_tf32(xs[(g    ) * XP + kl + tig    ]);
            uint32_t a1 = cvt_tf32(xs[(g + 8) * XP + kl + tig    ]);
            uint32_t a2 = cvt_tf32(xs[(g    ) * XP + kl + tig + 4]);
            uint32_t a3 = cvt_tf32(xs[(g + 8) * XP + kl + tig + 4]);

            float2 p0 = pb0[sg * 32];      // coalesced LDG.64 (L2-resident)
            mma_tf32(d0[0], d0[1], d0[2], d0[3], a0, a1, a2, a3,
                     __float_as_uint(p0.x), __float_as_uint(p0.y));

            float2 p1 = pb1[sg * 32];      // zeros for lanes g>=2
            mma_tf32(d1[0], d1[1], d1[2], d1[3], a0, a1, a2, a3,
                     __float_as_uint(p1.x), __float_as_uint(p1.y));
        }
        __syncwarp();                      // buffer reuse fence
    }

    // ---- epilogue: D c0,c1 -> (row g, cols 2tig,2tig+1); c2,c3 -> row g+8 ----
    {
        const int j0 = 2 * tig;
        float2 v;
        float* opA = out + (size_t)(wrow + g) * NOUT;
        float* opB = out + (size_t)(wrow + g + 8) * NOUT;
        v.x = d0[0] + cfs[j0];     v.y = d0[1] + cfs[j0 + 1];
        *(float2*)(opA + j0) = v;
        v.x = d0[2] + cfs[j0];     v.y = d0[3] + cfs[j0 + 1];
        *(float2*)(opB + j0) = v;
        if (tig == 0) {                    // j = 8,9
            v.x = d1[0] + cfs[8];  v.y = d1[1] + cfs[9];
            *(float2*)(opA + 8) = v;
            v.x = d1[2] + cfs[8];  v.y = d1[3] + cfs[9];
            *(float2*)(opB + 8) = v;
        }
    }
}

// ---------------------------------------------------------------------------
extern "C" void kernel_launch(void* const* d_in, const int* in_sizes, int n_in,
                              void* d_out, int out_size) {
    const float* x  = (const float*)d_in[0];
    const float* W0 = (const float*)d_in[1];
    const float* b0 = (const float*)d_in[2];
    const float* W1 = (const float*)d_in[3];
    const float* b1 = (const float*)d_in[4];
    const float* W2 = (const float*)d_in[5];
    const float* b2 = (const float*)d_in[6];
    const float* W3 = (const float*)d_in[7];
    const float* b3 = (const float*)d_in[8];
    const float* W4 = (const float*)d_in[9];
    const float* b4 = (const float*)d_in[10];
    const float* W5 = (const float*)d_in[11];
    const float* b5 = (const float*)d_in[12];
    const float* W6 = (const float*)d_in[13];
    const float* b6 = (const float*)d_in[14];
    const float* W7 = (const float*)d_in[15];
    const float* b7 = (const float*)d_in[16];
    const float* W8 = (const float*)d_in[17];
    const float* b8 = (const float*)d_in[18];
    float* out = (float*)d_out;

    static bool attr_set = false;
    const int smem_bytes = SM_TOTALF * sizeof(float);    // 104448 B
    if (!attr_set) {
        cudaFuncSetAttribute(mlp_mma, cudaFuncAttributeMaxDynamicSharedMemorySize,
                             smem_bytes);
        attr_set = true;
    }

    collapse_all<<<(KDIM * NOUT + CTPB - 1) / CTPB, CTPB>>>(
        W0, b0, W1, b1, W2, b2, W3, b3, W4, b4,
        W5, b5, W6, b6, W7, b7, W8, b8);

    mlp_mma<<<BSZ / ROWS_PER_BLOCK, MTPB, smem_bytes>>>(x, out);   // 512 blocks
}